// round 17
// baseline (speedup 1.0000x reference)
#include <cuda_runtime.h>
#include <mma.h>
#include <cuda_fp16.h>
#include <math.h>
#include <stdint.h>

using namespace nvcuda;

#define B_    2
#define S_    2048
#define NH_   16
#define HD_   128
#define NC_   32
#define QKVW  6144
#define NHD   2048

#define CS_LD 132
#define SS_LD 68

__device__ float g_qkv[(size_t)B_ * S_ * QKVW];
__device__ float g_kv[(size_t)B_ * NH_ * NC_ * HD_ * HD_];
__device__ float g_state[(size_t)B_ * NH_ * NC_ * HD_ * HD_];
__device__ float g_o[(size_t)B_ * S_ * NHD];
__device__ float g_gate[(size_t)B_ * S_ * NHD];
__device__ float g_rope[131072];
__device__ __half g_a2[8388608];
__device__ __half g_w2[20971520];

__device__ __forceinline__ float slope_for(int h) {
    return -exp2f(-0.5f * (float)(h + 1)) * (1.0f + 1e-5f);
}
__device__ __forceinline__ uint32_t smem_u32(const void* p) {
    uint32_t a;
    asm("{ .reg .u64 t; cvta.to.shared.u64 t, %1; cvt.u32.u64 %0, t; }" : "=r"(a) : "l"(p));
    return a;
}
__device__ __forceinline__ void cp_async16(uint32_t sa, const void* ga) {
    asm volatile("cp.async.cg.shared.global [%0], [%1], 16;" :: "r"(sa), "l"(ga));
}

__global__ void rope_tab_kernel() {
    int idx = blockIdx.x * 256 + threadIdx.x;
    int p = idx >> 5, j = idx & 31;
    float inv = exp2f(-(float)j * (13.287712379549449f / 32.0f));
    float ang = (float)p * inv;
    g_rope[idx]         = cosf(ang);
    g_rope[65536 + idx] = sinf(ang);
}

__global__ void round_Ah(const float* __restrict__ in, __half* __restrict__ out) {
    size_t idx = ((size_t)blockIdx.x * 256 + threadIdx.x) * 4;
    float4 v = *(const float4*)(in + idx);
    __half h[4];
    h[0] = __float2half_rn(v.x); h[1] = __float2half_rn(v.y);
    h[2] = __float2half_rn(v.z); h[3] = __float2half_rn(v.w);
    *(uint2*)(out + idx) = *(const uint2*)h;
}

__global__ void round_Bh(const float* __restrict__ in, __half* __restrict__ out,
                         int N, int ldo, int col_off) {
    size_t idx = ((size_t)blockIdx.x * 256 + threadIdx.x) * 4;
    int k = (int)(idx / N), n = (int)(idx % N);
    float4 v = *(const float4*)(in + idx);
    __half h[4];
    h[0] = __float2half_rn(v.x); h[1] = __float2half_rn(v.y);
    h[2] = __float2half_rn(v.z); h[3] = __float2half_rn(v.w);
    *(uint2*)(out + (size_t)k * ldo + col_off + n) = *(const uint2*)h;
}

#define AS_LD 72
#define BS_LD 136
#define STG_H (128 * AS_LD + 64 * BS_LD)

typedef wmma::fragment<wmma::matrix_a, 16, 16, 16, __half, wmma::row_major> FragA;
typedef wmma::fragment<wmma::matrix_b, 16, 16, 16, __half, wmma::row_major> FragB;

__global__ void __launch_bounds__(128, 2)
gemm_fp16(const __half* __restrict__ A, const __half* __restrict__ Bm,
          float* __restrict__ C1, float* __restrict__ C2,
          int M, int N1, int N2, int ldb)
{
    extern __shared__ __half smh[];

    const int tid = threadIdx.x, warp = tid >> 5;
    const int wr = warp >> 1, wc = warp & 1;
    const int bm = blockIdx.y * 128, bn = blockIdx.x * 128;

    __half* pA[3];
    __half* pB[3];
    uint32_t uA[3], uB[3];
#pragma unroll
    for (int s = 0; s < 3; s++) {
        pA[s] = smh + s * STG_H;
        pB[s] = pA[s] + 128 * AS_LD;
        uA[s] = smem_u32(pA[s]);
        uB[s] = smem_u32(pB[s]);
    }

    wmma::fragment<wmma::accumulator, 16, 16, 16, float> acc[4][4];
#pragma unroll
    for (int i = 0; i < 4; i++)
#pragma unroll
        for (int j = 0; j < 4; j++) wmma::fill_fragment(acc[i][j], 0.0f);

    auto load_stage = [&](int s, int i) {
        const int k0 = i << 6;
#pragma unroll
        for (int j = 0; j < 8; j++) {
            int id = tid + j * 128;
            int r = id >> 3, c = (id & 7) << 3;
            cp_async16(uA[s] + (uint32_t)(r * AS_LD + c) * 2u,
                       A + (size_t)(bm + r) * 2048 + k0 + c);
        }
#pragma unroll
        for (int j = 0; j < 8; j++) {
            int id = tid + j * 128;
            int r = id >> 4, c = (id & 15) << 3;
            cp_async16(uB[s] + (uint32_t)(r * BS_LD + c) * 2u,
                       Bm + (size_t)(k0 + r) * ldb + bn + c);
        }
        asm volatile("cp.async.commit_group;" ::: "memory");
    };

    const int nk = 32;
    load_stage(0, 0);
    load_stage(1, 1);

    for (int i = 0; i < nk; i++) {
        const int s = i % 3;
        if (i < nk - 1) {
            asm volatile("cp.async.wait_group 1;" ::: "memory");
        } else {
            asm volatile("cp.async.wait_group 0;" ::: "memory");
        }
        __syncthreads();
        if (i + 2 < nk) load_stage((i + 2) % 3, i + 2);

        const __half* a0 = pA[s] + wr * 64 * AS_LD;
        const __half* b0 = pB[s] + wc * 64;
#pragma unroll
        for (int kk = 0; kk < 64; kk += 16) {
            FragA af[4];
            FragB bf[4];
#pragma unroll
            for (int x = 0; x < 4; x++)
                wmma::load_matrix_sync(af[x], a0 + x * 16 * AS_LD + kk, AS_LD);
#pragma unroll
            for (int y = 0; y < 4; y++)
                wmma::load_matrix_sync(bf[y], b0 + kk * BS_LD + y * 16, BS_LD);
#pragma unroll
            for (int x = 0; x < 4; x++)
#pragma unroll
                for (int y = 0; y < 4; y++)
                    wmma::mma_sync(acc[x][y], af[x], bf[y], acc[x][y]);
        }
    }

    if (bn < N1) {
#pragma unroll
        for (int x = 0; x < 4; x++)
#pragma unroll
            for (int y = 0; y < 4; y++)
                wmma::store_matrix_sync(C1 + (size_t)(bm + wr * 64 + x * 16) * N1 + bn + wc * 64 + y * 16,
                                        acc[x][y], N1, wmma::mem_row_major);
    } else {
        const int bn2 = bn - N1;
#pragma unroll
        for (int x = 0; x < 4; x++)
#pragma unroll
            for (int y = 0; y < 4; y++)
                wmma::store_matrix_sync(C2 + (size_t)(bm + wr * 64 + x * 16) * N2 + bn2 + wc * 64 + y * 16,
                                        acc[x][y], N2, wmma::mem_row_major);
    }
}

__device__ __forceinline__ void norm_rope_tile(float* st, const float* __restrict__ w,
                                               const int* __restrict__ positions,
                                               int c, int tid)
{
    const int r = tid >> 2, t4 = tid & 3;
    float ss = 0.0f;
#pragma unroll 8
    for (int d = t4 * 32; d < t4 * 32 + 32; d++) {
        float a = st[r * CS_LD + d];
        ss += a * a;
    }
    ss += __shfl_xor_sync(0xffffffffu, ss, 1);
    ss += __shfl_xor_sync(0xffffffffu, ss, 2);
    float f = rsqrtf(ss * (1.0f / 128.0f) + 1e-6f);
#pragma unroll 8
    for (int d = t4 * 32; d < t4 * 32 + 32; d++)
        st[r * CS_LD + d] *= f * w[d];
    __syncthreads();
    for (int p = tid; p < 64 * 32; p += 256) {
        int rr = p >> 5, j = p & 31;
        int pos = positions[c * 64 + rr];
        float cs = g_rope[pos * 32 + j];
        float sn = g_rope[65536 + pos * 32 + j];
        float x1 = st[rr * CS_LD + j], x2 = st[rr * CS_LD + j + 32];
        st[rr * CS_LD + j]      = x1 * cs - x2 * sn;
        st[rr * CS_LD + j + 32] = x2 * cs + x1 * sn;
    }
    __syncthreads();
}

__global__ void __launch_bounds__(256, 2) chunk_stats_kernel(
    const float* __restrict__ qnw, const float* __restrict__ knw,
    const int* __restrict__ positions)
{
    extern __shared__ float sm[];
    float* sK   = sm;
    float* sQV  = sm + 64 * CS_LD;
    float* sS   = sm + 2 * 64 * CS_LD;
    float* sdec = sS + 64 * SS_LD;

    const int bhc = blockIdx.x;
    const int c = bhc & 31, h = (bhc >> 5) & 15, b = bhc >> 9;
    const int tid = threadIdx.x;
    const float slope = slope_for(h);
    const int ty = tid >> 4, tx = tid & 15;

    const size_t rowbase = ((size_t)(b * S_) + c * 64) * QKVW + h * HD_;

    for (int f = tid; f < 2048; f += 256) {
        int i = f >> 5, d4 = (f & 31) << 2;
        const float* gp = g_qkv + rowbase + (size_t)i * QKVW + d4;
        *(float4*)(sQV + i * CS_LD + d4) = *(const float4*)(gp);
        *(float4*)(sK  + i * CS_LD + d4) = *(const float4*)(gp + 2048);
    }
    if (tid < 64) sdec[tid] = expf(slope * (float)(63 - tid));
    __syncthreads();

    norm_rope_tile(sQV, qnw, positions, c, tid);
    norm_rope_tile(sK,  knw, positions, c, tid);

    for (int f = tid; f < 2048; f += 256) {
        int i = f >> 5, d4 = (f & 31) << 2;
        *(float4*)(g_qkv + rowbase + (size_t)i * QKVW + d4) =
            *(const float4*)(sQV + i * CS_LD + d4);
    }

    {
        float a[4][4] = {};
        const int i0 = ty * 4, j0 = tx * 4;
        for (int d = 0; d < 128; d += 4) {
            float4 q[4], kk[4];
#pragma unroll
            for (int r = 0; r < 4; r++) q[r] = *(const float4*)(sQV + (i0 + r) * CS_LD + d);
#pragma unroll
            for (int cc = 0; cc < 4; cc++) kk[cc] = *(const float4*)(sK + (j0 + cc) * CS_LD + d);
#pragma unroll
            for (int r = 0; r < 4; r++)
#pragma unroll
                for (int cc = 0; cc < 4; cc++)
                    a[r][cc] += q[r].x * kk[cc].x + q[r].y * kk[cc].y
                              + q[r].z * kk[cc].z + q[r].w * kk[cc].w;
        }
#pragma unroll
        for (int r = 0; r < 4; r++)
#pragma unroll
            for (int cc = 0; cc < 4; cc++) {
                int i = i0 + r, j = j0 + cc;
                sS[i * SS_LD + j] = (i >= j) ? a[r][cc] * expf(slope * (float)(i - j)) : 0.0f;
            }
    }
    __syncthreads();

    for (int f = tid; f < 2048; f += 256) {
        int i = f >> 5, d4 = (f & 31) << 2;
        *(float4*)(sQV + i * CS_LD + d4) =
            *(const float4*)(g_qkv + rowbase + (size_t)i * QKVW + 4096 + d4);
        float kd = sdec[i];
        float4 k = *(const float4*)(sK + i * CS_LD + d4);
        k.x *= kd; k.y *= kd; k.z *= kd; k.w *= kd;
        *(float4*)(sK + i * CS_LD + d4) = k;
    }
    __syncthreads();

    const size_t obase = ((size_t)(b * S_) + c * 64) * NHD + h * HD_;
    {
        float a0[4][4] = {}, a1[4][4] = {};
        const int i0 = ty * 4, e0 = tx * 4;
        for (int j = 0; j < 64; j += 4) {
            float4 s4[4];
#pragma unroll
            for (int r = 0; r < 4; r++) s4[r] = *(const float4*)(sS + (i0 + r) * SS_LD + j);
#pragma unroll
            for (int jj = 0; jj < 4; jj++) {
                float4 v0 = *(const float4*)(sQV + (j + jj) * CS_LD + e0);
                float4 v1 = *(const float4*)(sQV + (j + jj) * CS_LD + e0 + 64);
                float sv[4];
                sv[0] = ((const float*)&s4[0])[jj];
                sv[1] = ((const float*)&s4[1])[jj];
                sv[2] = ((const float*)&s4[2])[jj];
                sv[3] = ((const float*)&s4[3])[jj];
#pragma unroll
                for (int r = 0; r < 4; r++) {
                    a0[r][0] += sv[r] * v0.x; a0[r][1] += sv[r] * v0.y;
                    a0[r][2] += sv[r] * v0.z; a0[r][3] += sv[r] * v0.w;
                    a1[r][0] += sv[r] * v1.x; a1[r][1] += sv[r] * v1.y;
                    a1[r][2] += sv[r] * v1.z; a1[r][3] += sv[r] * v1.w;
                }
            }
        }
#pragma unroll
        for (int r = 0; r < 4; r++) {
            *(float4*)(g_o + obase + (size_t)(i0 + r) * NHD + e0)      = *(const float4*)a0[r];
            *(float4*)(g_o + obase + (size_t)(i0 + r) * NHD + e0 + 64) = *(const float4*)a1[r];
        }
    }

    {
        float a0[8][4] = {}, a1[8][4] = {};
        const int d0 = ty * 8, e0 = tx * 4;
        for (int j = 0; j < 64; j++) {
            float4 ka = *(const float4*)(sK + j * CS_LD + d0);
            float4 kb = *(const float4*)(sK + j * CS_LD + d0 + 4);
            float4 v0 = *(const float4*)(sQV + j * CS_LD + e0);
            float4 v1 = *(const float4*)(sQV + j * CS_LD + e0 + 64);
            float kr[8] = { ka.x, ka.y, ka.z, ka.w, kb.x, kb.y, kb.z, kb.w };
#pragma unroll
            for (int r = 0; r < 8; r++) {
                a0[r][0] += kr[r] * v0.x; a0[r][1] += kr[r] * v0.y;
                a0[r][2] += kr[r] * v0.z; a0[r][3] += kr[r] * v0.w;
                a1[r][0] += kr[r] * v1.x; a1[r][1] += kr[r] * v1.y;
                a1[r][2] += kr[r] * v1.z; a1[r][3] += kr[r] * v1.w;
            }
        }
        const size_t kvbase = ((size_t)((b * 16 + h) * 32 + c)) * (HD_ * HD_);
#pragma unroll
        for (int r = 0; r < 8; r++) {
            *(float4*)(g_kv + kvbase + (size_t)(d0 + r) * HD_ + e0)      = *(const float4*)a0[r];
            *(float4*)(g_kv + kvbase + (size_t)(d0 + r) * HD_ + e0 + 64) = *(const float4*)a1[r];
        }
    }
}

__global__ void scan_kernel(const float* __restrict__ rec)
{
    const int bh = blockIdx.x >> 6;
    const int e  = ((blockIdx.x & 63) << 8) + threadIdx.x;
    const float lam = expf(slope_for(bh & 15) * 64.0f);

    float st = rec[(size_t)bh * 16384 + e];
    size_t base = (size_t)bh * 32 * 16384 + e;
#pragma unroll 4
    for (int c = 0; c < 32; c++) {
        g_state[base + (size_t)c * 16384] = st;
        st = st * lam + g_kv[base + (size_t)c * 16384];
    }
}

__global__ void __launch_bounds__(256, 2) o_inter_kernel(const int* __restrict__ positions)
{
    extern __shared__ float sm2[];
    float* sQ  = sm2;
    float* sST = sm2 + 64 * CS_LD;

    const int bhc = blockIdx.x;
    const int c = bhc & 31, h = (bhc >> 5) & 15, b = bhc >> 9;
    const int tid = threadIdx.x;
    const float slope = slope_for(h);
    const int ty = tid >> 4, tx = tid & 15;

    const size_t rowbase = ((size_t)(b * S_) + c * 64) * QKVW + h * HD_;
    for (int f = tid; f < 2048; f += 256) {
        int i = f >> 5, d4 = (f & 31) << 2;
        float4 q = *(const float4*)(g_qkv + rowbase + (size_t)i * QKVW + d4);
        float qd = expf(slope * (float)(i + 1));
        q.x *= qd; q.y *= qd; q.z *= qd; q.w *= qd;
        *(float4*)(sQ + i * CS_LD + d4) = q;
    }
    const float* st = g_state + ((size_t)((b * 16 + h) * 32 + c)) * (HD_ * HD_);
    for (int f = tid; f < 4096; f += 256) {
        int r = f >> 5, e4 = (f & 31) << 2;
        *(float4*)(sST + r * CS_LD + e4) = *(const float4*)(st + (size_t)r * HD_ + e4);
    }
    __syncthreads();

    float a0[4][4] = {}, a1[4][4] = {};
    const int i0 = ty * 4, e0 = tx * 4;
    for (int d = 0; d < 128; d += 4) {
        float4 q4[4];
#pragma unroll
        for (int r = 0; r < 4; r++) q4[r] = *(const float4*)(sQ + (i0 + r) * CS_LD + d);
#pragma unroll
        for (int dd = 0; dd < 4; dd++) {
            float4 s0 = *(const float4*)(sST + (d + dd) * CS_LD + e0);
            float4 s1 = *(const float4*)(sST + (d + dd) * CS_LD + e0 + 64);
            float qv[4];
            qv[0] = ((const float*)&q4[0])[dd];
            qv[1] = ((const float*)&q4[1])[dd];
            qv[2] = ((const float*)&q4[2])[dd];
            qv[3] = ((const float*)&q4[3])[dd];
#pragma unroll
            for (int r = 0; r < 4; r++) {
                a0[r][0] += qv[r] * s0.x; a0[r][1] += qv[r] * s0.y;
                a0[r][2] += qv[r] * s0.z; a0[r][3] += qv[r] * s0.w;
                a1[r][0] += qv[r] * s1.x; a1[r][1] += qv[r] * s1.y;
                a1[r][2] += qv[r] * s1.z; a1[r][3] += qv[r] * s1.w;
            }
        }
    }
    const size_t obase = ((size_t)(b * S_) + c * 64) * NHD + h * HD_;
#pragma unroll
    for (int r = 0; r < 4; r++) {
        float4 o0 = *(const float4*)(g_o + obase + (size_t)(i0 + r) * NHD + e0);
        float4 o1 = *(const float4*)(g_o + obase + (size_t)(i0 + r) * NHD + e0 + 64);
        o0.x += a0[r][0]; o0.y += a0[r][1]; o0.z += a0[r][2]; o0.w += a0[r][3];
        o1.x += a1[r][0]; o1.y += a1[r][1]; o1.z += a1[r][2]; o1.w += a1[r][3];
        *(float4*)(g_o + obase + (size_t)(i0 + r) * NHD + e0)      = o0;
        *(float4*)(g_o + obase + (size_t)(i0 + r) * NHD + e0 + 64) = o1;
    }
}

__global__ void gating_split_kernel(const float* __restrict__ gnw,
                                    __half* __restrict__ a2)
{
    const int row = blockIdx.x;
    const int w = threadIdx.x >> 5, l = threadIdx.x & 31;
    const int col = w * 256 + l * 8;

    const float* op = g_o    + (size_t)row * NHD + col;
    const float* gp = g_gate + (size_t)row * NHD + col;
    const float* wp = gnw    + col;

    float4 a0 = *(const float4*)(op);
    float4 a1 = *(const float4*)(op + 4);
    float ss = a0.x * a0.x + a0.y * a0.y + a0.z * a0.z + a0.w * a0.w
             + a1.x * a1.x + a1.y * a1.y + a1.z * a1.z + a1.w * a1.w;
#pragma unroll
    for (int o = 16; o > 0; o >>= 1) ss += __shfl_xor_sync(0xffffffffu, ss, o);
    float scale = rsqrtf(ss * (1.0f / 256.0f) + 1e-6f);

    float4 g0 = *(const float4*)(gp);
    float4 g1 = *(const float4*)(gp + 4);
    float4 w0 = *(const float4*)(wp);
    float4 w1 = *(const float4*)(wp + 4);

    __half h[8];
    h[0] = __float2half_rn(a0.x * scale * w0.x / (1.0f + expf(-g0.x)));
    h[1] = __float2half_rn(a0.y * scale * w0.y / (1.0f + expf(-g0.y)));
    h[2] = __float2half_rn(a0.z * scale * w0.z / (1.0f + expf(-g0.z)));
    h[3] = __float2half_rn(a0.w * scale * w0.w / (1.0f + expf(-g0.w)));
    h[4] = __float2half_rn(a1.x * scale * w1.x / (1.0f + expf(-g1.x)));
    h[5] = __float2half_rn(a1.y * scale * w1.y / (1.0f + expf(-g1.y)));
    h[6] = __float2half_rn(a1.z * scale * w1.z / (1.0f + expf(-g1.z)));
    h[7] = __float2half_rn(a1.w * scale * w1.w / (1.0f + expf(-g1.w)));

    *(uint4*)(a2 + (size_t)row * 2048 + col) = *(const uint4*)h;
}

extern "C" void kernel_launch(void* const* d_in, const int* in_sizes, int n_in,
                              void* d_out, int out_size)
{
    const int*   positions = (const int*)d_in[0];
    const float* hidden    = (const float*)d_in[1];
    const float* rec       = (const float*)d_in[2];
    const float* w_qkv     = (const float*)d_in[3];
    const float* w_g       = (const float*)d_in[4];
    const float* w_dense   = (const float*)d_in[5];
    const float* qnw       = (const float*)d_in[6];
    const float* knw       = (const float*)d_in[7];
    const float* gnw       = (const float*)d_in[8];
    float* out = (float*)d_out;

    float *qkvp, *op, *gatep;
    __half *a2p, *w2p;
    cudaGetSymbolAddress((void**)&qkvp,  g_qkv);
    cudaGetSymbolAddress((void**)&op,    g_o);
    cudaGetSymbolAddress((void**)&gatep, g_gate);
    cudaGetSymbolAddress((void**)&a2p,   g_a2);
    cudaGetSymbolAddress((void**)&w2p,   g_w2);
    __half* wF = w2p;
    __half* wD = w2p + 16777216;

    const int GSM   = 3 * STG_H * 2;
    const int SMEM3 = (2 * 64 * CS_LD + 64 * SS_LD + 64) * 4;
    const int SMEM6 = (64 * CS_LD + 128 * CS_LD) * 4;
    cudaFuncSetAttribute(gemm_fp16, cudaFuncAttributeMaxDynamicSharedMemorySize, GSM);
    cudaFuncSetAttribute(chunk_stats_kernel, cudaFuncAttributeMaxDynamicSharedMemorySize, SMEM3);
    cudaFuncSetAttribute(o_inter_kernel, cudaFuncAttributeMaxDynamicSharedMemorySize, SMEM6);

    round_Ah<<<8192, 256>>>(hidden, a2p);
    round_Bh<<<12288, 256>>>(w_qkv, wF, 6144, 8192, 0);
    round_Bh<<<4096, 256>>>(w_g, wF, 2048, 8192, 6144);
    gemm_fp16<<<dim3(64, 32), 128, GSM>>>(a2p, wF, qkvp, gatep, 4096, QKVW, NHD, 8192);
    rope_tab_kernel<<<256, 256>>>();
    chunk_stats_kernel<<<B_ * NH_ * NC_, 256, SMEM3>>>(qnw, knw, positions);
    scan_kernel<<<2048, 256>>>(rec);
    o_inter_kernel<<<B_ * NH_ * NC_, 256, SMEM6>>>(positions);
    round_Bh<<<4096, 256>>>(w_dense, wD, 2048, 2048, 0);
    gating_split_kernel<<<B_ * S_, 256>>>(gnw, a2p);
    gemm_fp16<<<dim3(16, 32), 128, GSM>>>(a2p, wD, out, nullptr, 4096, NHD, 0, 2048);
}